// round 2
// baseline (speedup 1.0000x reference)
#include <cuda_runtime.h>

// ---------------- problem constants ----------------
#define BB    64      // batch
#define NSP   49      // spatial positions
#define ENC   1024
#define DEC   512
#define EMBD  512
#define VOC   10000
#define MSN   8       // max sentences
#define MWN   20      // max words
#define BW    512     // MSN*BB : batched word-RNN rows
#define G3    1536    // 3*DEC

// ---------------- device scratch (static, no allocation) ----------------
__device__ float d_gf   [BB * ENC];
__device__ float d_hs   [BB * DEC];
__device__ float d_gis  [BB * G3];
__device__ float d_ghs  [BB * G3];
__device__ float d_HS   [MSN * BB * DEC];
__device__ float d_att1 [BB * NSP * EMBD];
__device__ float d_EMBT [MWN * BW * EMBD];
__device__ float d_EMBGI[MWN * BW * G3];
__device__ float d_H    [BW * DEC];
__device__ float d_Hall [MWN * BW * DEC];
__device__ float d_att2 [BW * EMBD];
__device__ float d_ctx  [BW * ENC];
__device__ float d_gictx[BW * G3];
__device__ float d_ghw  [BW * G3];

// ---------------- generic tiled SGEMM: C = act(A @ W^T + bias) ----------------
// A: [M,K] row-major (lda), W: [N,K] row-major (ldw), C: [M,N] (ldc).
// Requires K % 16 == 0 (true for all calls: K in {512, 1024}).
template <int ACT>   // 0 = none, 1 = tanh
__global__ void __launch_bounds__(256)
sgemm_tn(const float* __restrict__ A, int lda,
         const float* __restrict__ W, int ldw,
         const float* __restrict__ bias,
         float* __restrict__ C, int ldc,
         int M, int N, int K)
{
    __shared__ float As[16][68];
    __shared__ float Bs[16][68];

    const int m0  = blockIdx.x * 64;
    const int n0  = blockIdx.y * 64;
    const int tid = threadIdx.x;
    const int tx  = tid & 15;       // n sub-tile
    const int ty  = tid >> 4;       // m sub-tile

    const int lrow = tid >> 2;          // 0..63  row loaded by this thread
    const int lcol = (tid & 3) * 4;     // 0,4,8,12

    const bool aval = (m0 + lrow) < M;
    const bool wval = (n0 + lrow) < N;
    const float* Ap = A + (size_t)(m0 + lrow) * lda + lcol;
    const float* Wp = W + (size_t)(n0 + lrow) * ldw + lcol;

    float acc[4][4] = {};

    for (int k0 = 0; k0 < K; k0 += 16) {
        float4 av = aval ? *(const float4*)(Ap + k0) : make_float4(0.f, 0.f, 0.f, 0.f);
        float4 wv = wval ? *(const float4*)(Wp + k0) : make_float4(0.f, 0.f, 0.f, 0.f);
        As[lcol + 0][lrow] = av.x; As[lcol + 1][lrow] = av.y;
        As[lcol + 2][lrow] = av.z; As[lcol + 3][lrow] = av.w;
        Bs[lcol + 0][lrow] = wv.x; Bs[lcol + 1][lrow] = wv.y;
        Bs[lcol + 2][lrow] = wv.z; Bs[lcol + 3][lrow] = wv.w;
        __syncthreads();
#pragma unroll
        for (int kk = 0; kk < 16; kk++) {
            float4 a = *(const float4*)&As[kk][ty * 4];
            float4 b = *(const float4*)&Bs[kk][tx * 4];
            acc[0][0] += a.x * b.x; acc[0][1] += a.x * b.y; acc[0][2] += a.x * b.z; acc[0][3] += a.x * b.w;
            acc[1][0] += a.y * b.x; acc[1][1] += a.y * b.y; acc[1][2] += a.y * b.z; acc[1][3] += a.y * b.w;
            acc[2][0] += a.z * b.x; acc[2][1] += a.z * b.y; acc[2][2] += a.z * b.z; acc[2][3] += a.z * b.w;
            acc[3][0] += a.w * b.x; acc[3][1] += a.w * b.y; acc[3][2] += a.w * b.z; acc[3][3] += a.w * b.w;
        }
        __syncthreads();
    }

#pragma unroll
    for (int i = 0; i < 4; i++) {
        int m = m0 + ty * 4 + i;
        if (m >= M) continue;
#pragma unroll
        for (int j = 0; j < 4; j++) {
            int n = n0 + tx * 4 + j;
            if (n >= N) continue;
            float v = acc[i][j] + (bias ? bias[n] : 0.f);
            if (ACT == 1) v = tanhf(v);
            C[(size_t)m * ldc + n] = v;
        }
    }
}

// ---------------- small kernels ----------------
__global__ void mean_kernel(const float* __restrict__ sp)
{
    int b = blockIdx.x;
    for (int e = threadIdx.x; e < ENC; e += blockDim.x) {
        float s = 0.f;
        for (int n = 0; n < NSP; n++) s += sp[((size_t)b * NSP + n) * ENC + e];
        d_gf[b * ENC + e] = s * (1.0f / 49.0f);
    }
}

__device__ __forceinline__ float sigmf(float x) { return 1.0f / (1.0f + expf(-x)); }

__global__ void sgru_gate(int i)
{
    int b = blockIdx.x, j = threadIdx.x;
    float gr = d_gis[b * G3 + j]            + d_ghs[b * G3 + j];
    float gz = d_gis[b * G3 + DEC + j]      + d_ghs[b * G3 + DEC + j];
    float gni = d_gis[b * G3 + 2 * DEC + j];
    float gnh = d_ghs[b * G3 + 2 * DEC + j];
    float h  = d_hs[b * DEC + j];
    float r  = sigmf(gr);
    float z  = sigmf(gz);
    float n  = tanhf(gni + r * gnh);
    float hn = (1.0f - z) * n + z * h;
    d_hs[b * DEC + j] = hn;
    d_HS[(size_t)i * BB * DEC + b * DEC + j] = hn;
}

__global__ void policy_stop_kernel(const float* __restrict__ pW, const float* __restrict__ pb,
                                   const float* __restrict__ sW, const float* __restrict__ sb,
                                   float* __restrict__ out)
{
    int row = blockIdx.x;            // i*BB + b (HS row)
    int i = row >> 6, b = row & 63;
    int warp = threadIdx.x >> 5, lane = threadIdx.x & 31;
    const float* h = d_HS + (size_t)row * DEC;
    const float* w = (warp < 5) ? (pW + warp * DEC) : sW;
    float s = 0.f;
    for (int k = lane; k < DEC; k += 32) s += h[k] * w[k];
#pragma unroll
    for (int o = 16; o; o >>= 1) s += __shfl_xor_sync(0xffffffff, s, o);
    if (lane == 0) {
        if (warp < 5) out[(b * MSN + i) * 5 + warp] = s + pb[warp];
        else          out[BB * MSN * 5 + b * MSN + i] = s + sb[0];
    }
}

__global__ void gather_emb(const int* __restrict__ tw, const float* __restrict__ embW)
{
    int idx = blockIdx.x * blockDim.x + threadIdx.x;
    const int total = MWN * BW * (EMBD / 4);        // 1,310,720
    if (idx >= total) return;
    int c4 = idx & 127;
    int r  = (idx >> 7) & 511;
    int t  = idx >> 16;
    int b = r & 63, s = r >> 6;
    int w = (t == 0) ? 1 : tw[b * MSN * MWN + s * MWN + (t - 1)];
    float4 v = *(const float4*)(embW + (size_t)w * EMBD + c4 * 4);
    *(float4*)(&d_EMBT[((size_t)t * BW + r) * EMBD + c4 * 4]) = v;
}

__global__ void copyH_kernel()
{
    int i = blockIdx.x * blockDim.x + threadIdx.x;
    d_H[i] = d_HS[i];
}

// attention for one word step: e = relu(att1[b] + att2[r]) . wfull + bf ; softmax; ctx
__global__ void __launch_bounds__(256)
attn_kernel(const float* __restrict__ sp,
            const float* __restrict__ wfull, const float* __restrict__ bfull)
{
    __shared__ float a2[EMBD];
    __shared__ float e[64];
    __shared__ float alpha[64];

    int r = blockIdx.x;
    int b = r & (BB - 1);
    int tid = threadIdx.x;
    int warp = tid >> 5, lane = tid & 31;

    for (int k = tid; k < EMBD; k += 256) a2[k] = d_att2[(size_t)r * EMBD + k];
    __syncthreads();

    for (int n = warp; n < NSP; n += 8) {
        const float* a1 = d_att1 + ((size_t)(b * NSP + n)) * EMBD;
        float s = 0.f;
        for (int k = lane; k < EMBD; k += 32) {
            float v = a1[k] + a2[k];
            v = fmaxf(v, 0.f);
            s += v * wfull[k];
        }
#pragma unroll
        for (int o = 16; o; o >>= 1) s += __shfl_xor_sync(0xffffffff, s, o);
        if (lane == 0) e[n] = s + bfull[0];
    }
    __syncthreads();

    if (warp == 0) {
        float m = -1e30f;
        for (int n = lane; n < NSP; n += 32) m = fmaxf(m, e[n]);
#pragma unroll
        for (int o = 16; o; o >>= 1) m = fmaxf(m, __shfl_xor_sync(0xffffffff, m, o));
        float ssum = 0.f;
        for (int n = lane; n < NSP; n += 32) { float t = expf(e[n] - m); alpha[n] = t; ssum += t; }
#pragma unroll
        for (int o = 16; o; o >>= 1) ssum += __shfl_xor_sync(0xffffffff, ssum, o);
        float inv = 1.0f / ssum;
        for (int n = lane; n < NSP; n += 32) alpha[n] *= inv;
    }
    __syncthreads();

    for (int c = tid; c < ENC; c += 256) {
        float s = 0.f;
#pragma unroll 7
        for (int n = 0; n < NSP; n++) s += alpha[n] * sp[((size_t)(b * NSP + n)) * ENC + c];
        d_ctx[(size_t)r * ENC + c] = s;
    }
}

__global__ void wgru_gate(int t)
{
    int r = blockIdx.x, j = threadIdx.x;
    size_t eb = ((size_t)t * BW + r) * G3;
    size_t rb = (size_t)r * G3;
    float gir = d_EMBGI[eb + j]           + d_gictx[rb + j];
    float giz = d_EMBGI[eb + DEC + j]     + d_gictx[rb + DEC + j];
    float gin = d_EMBGI[eb + 2 * DEC + j] + d_gictx[rb + 2 * DEC + j];
    float ghr = d_ghw[rb + j];
    float ghz = d_ghw[rb + DEC + j];
    float ghn = d_ghw[rb + 2 * DEC + j];
    float h   = d_H[(size_t)r * DEC + j];
    float rg = sigmf(gir + ghr);
    float z  = sigmf(giz + ghz);
    float n  = tanhf(gin + rg * ghn);
    float hn = (1.0f - z) * n + z * h;
    d_H[(size_t)r * DEC + j] = hn;
    int b = r & 63, s = r >> 6;
    d_Hall[((size_t)((b * MSN + s) * MWN + t)) * DEC + j] = hn;
}

// ---------------- cached scratch addresses (resolved once, on the
// correctness call, which runs OUTSIDE graph capture; capture call is
// then a pure launch sequence) ----------------
static float *gf, *hs, *gis, *ghs, *att1, *embt, *embgi, *H, *Hall,
             *att2, *ctx, *gictx, *ghw;
static bool g_init = false;

static void resolve_scratch()
{
    cudaGetSymbolAddress((void**)&gf,    d_gf);
    cudaGetSymbolAddress((void**)&hs,    d_hs);
    cudaGetSymbolAddress((void**)&gis,   d_gis);
    cudaGetSymbolAddress((void**)&ghs,   d_ghs);
    cudaGetSymbolAddress((void**)&att1,  d_att1);
    cudaGetSymbolAddress((void**)&embt,  d_EMBT);
    cudaGetSymbolAddress((void**)&embgi, d_EMBGI);
    cudaGetSymbolAddress((void**)&H,     d_H);
    cudaGetSymbolAddress((void**)&Hall,  d_Hall);
    cudaGetSymbolAddress((void**)&att2,  d_att2);
    cudaGetSymbolAddress((void**)&ctx,   d_ctx);
    cudaGetSymbolAddress((void**)&gictx, d_gictx);
    cudaGetSymbolAddress((void**)&ghw,   d_ghw);
    g_init = true;
}

// ---------------- host launcher ----------------
extern "C" void kernel_launch(void* const* d_in, const int* in_sizes, int n_in,
                              void* d_out, int out_size)
{
    if (!g_init) resolve_scratch();

    const float* spatial    = (const float*)d_in[0];
    const int*   tw         = (const int*)  d_in[1];
    const float* emb_W      = (const float*)d_in[2];
    const float* s_W_ih     = (const float*)d_in[3];
    const float* s_W_hh     = (const float*)d_in[4];
    const float* s_b_ih     = (const float*)d_in[5];
    const float* s_b_hh     = (const float*)d_in[6];
    const float* policy_W   = (const float*)d_in[7];
    const float* policy_b   = (const float*)d_in[8];
    const float* stop_W     = (const float*)d_in[9];
    const float* stop_b     = (const float*)d_in[10];
    const float* att_enc_W  = (const float*)d_in[11];
    const float* att_enc_b  = (const float*)d_in[12];
    const float* att_dec_W  = (const float*)d_in[13];
    const float* att_dec_b  = (const float*)d_in[14];
    const float* att_full_W = (const float*)d_in[15];
    const float* att_full_b = (const float*)d_in[16];
    const float* w_W_ih     = (const float*)d_in[17];
    const float* w_W_hh     = (const float*)d_in[18];
    const float* w_b_ih     = (const float*)d_in[19];
    const float* w_b_hh     = (const float*)d_in[20];
    const float* fc_W       = (const float*)d_in[21];
    const float* fc_b       = (const float*)d_in[22];
    const float* init_W     = (const float*)d_in[23];
    const float* init_b     = (const float*)d_in[24];
    float* out = (float*)d_out;

    // ---- setup ----
    mean_kernel<<<BB, 256>>>(spatial);
    // h0 = tanh(gf @ init_W.T + init_b)
    sgemm_tn<1><<<dim3(1, 8), 256>>>(gf, ENC, init_W, ENC, init_b, hs, DEC, BB, DEC, ENC);
    // att1 = spatial @ att_enc_W.T + att_enc_b
    sgemm_tn<0><<<dim3(49, 8), 256>>>(spatial, ENC, att_enc_W, ENC, att_enc_b,
                                      att1, EMBD, BB * NSP, EMBD, ENC);
    // gi_s constant across sentence steps
    sgemm_tn<0><<<dim3(1, 24), 256>>>(gf, ENC, s_W_ih, ENC, s_b_ih, gis, G3, BB, G3, ENC);

    // ---- sentence GRU: 8 tiny sequential steps ----
    for (int i = 0; i < MSN; i++) {
        sgemm_tn<0><<<dim3(1, 24), 256>>>(hs, DEC, s_W_hh, DEC, s_b_hh, ghs, G3, BB, G3, DEC);
        sgru_gate<<<BB, DEC>>>(i);
    }
    policy_stop_kernel<<<MSN * BB, 192>>>(policy_W, policy_b, stop_W, stop_b, out);

    // ---- batched precomputes for word RNN ----
    gather_emb<<<(MWN * BW * (EMBD / 4) + 255) / 256, 256>>>(tw, emb_W);
    // EMBGI[t] = emb_t @ W_ih[:, :EMB].T + b_ih  (all 20 steps at once)
    sgemm_tn<0><<<dim3(160, 24), 256>>>(embt, EMBD, w_W_ih, G3, w_b_ih,
                                        embgi, G3, MWN * BW, G3, EMBD);
    copyH_kernel<<<512, 512>>>();   // H init = HS (identical layout)

    // ---- word RNN: 20 sequential steps over 512 batched rows ----
    for (int t = 0; t < MWN; t++) {
        sgemm_tn<0><<<dim3(8, 8), 256>>>(H, DEC, att_dec_W, DEC, att_dec_b,
                                         att2, EMBD, BW, EMBD, DEC);
        attn_kernel<<<BW, 256>>>(spatial, att_full_W, att_full_b);
        sgemm_tn<0><<<dim3(8, 24), 256>>>(ctx, ENC, w_W_ih + EMBD, G3, (const float*)nullptr,
                                          gictx, G3, BW, G3, ENC);
        sgemm_tn<0><<<dim3(8, 24), 256>>>(H, DEC, w_W_hh, DEC, w_b_hh,
                                          ghw, G3, BW, G3, DEC);
        wgru_gate<<<BW, DEC>>>(t);
    }

    // ---- final vocab projection: one big GEMM straight into the output ----
    // word output rows ordered (b, s, t) match Hall rows; offset past policy+stop
    sgemm_tn<0><<<dim3(160, 157), 256>>>(Hall, DEC, fc_W, DEC, fc_b,
                                         out + 3072, VOC, MWN * BW, VOC, DEC);
}

// round 3
// speedup vs baseline: 1.2848x; 1.2848x over previous
#include <cuda_runtime.h>
#include <mma.h>
using namespace nvcuda;

// ---------------- problem constants ----------------
#define BB    64      // batch
#define NSP   49      // spatial positions
#define ENC   1024
#define DEC   512
#define EMBD  512
#define VOC   10000
#define MSN   8       // max sentences
#define MWN   20      // max words
#define BW    512     // MSN*BB : batched word-RNN rows
#define G3    1536    // 3*DEC

// ---------------- device scratch (static, no allocation) ----------------
__device__ float d_gf   [BB * ENC];
__device__ float d_hs   [BB * DEC];
__device__ float d_gis  [BB * G3];
__device__ float d_ghs  [BB * G3];
__device__ float d_HS   [MSN * BB * DEC];
__device__ float d_att1 [BB * NSP * EMBD];
__device__ float d_EMBT [MWN * BW * EMBD];
__device__ float d_EMBGI[MWN * BW * G3];
__device__ float d_H    [BW * DEC];
__device__ float d_Hall [MWN * BW * DEC];
__device__ float d_att2 [BW * EMBD];
__device__ float d_ctx  [BW * ENC];
__device__ float d_gictx[BW * G3];
__device__ float d_ghw  [BW * G3];

// ================= tf32 tensor-core GEMM: C = A @ W^T + bias =================
// A: [M,K] row-major (lda), W: [N,K] row-major (ldw), C: [M,N] (ldc).
// Block tile 128x80, 4 warps, warp tile 32x80 (2x5 wmma 16x16k8 frags).
// K must be a multiple of 32. Values pre-rounded to tf32 (RNA) in smem.
#define TMM 128
#define TNN 80
#define TKK 32
#define AS_LD 36
#define WS_LD 36
#define CS_LD 84
#define MMA_SMEM_BYTES (TMM * CS_LD * 4)   // 43008 B  (>= (TMM+TNN)*36*4)

__global__ void __launch_bounds__(128)
mma_gemm(const float* __restrict__ A, int lda,
         const float* __restrict__ W, int ldw,
         const float* __restrict__ bias,
         float* __restrict__ C, int ldc,
         int M, int N, int K)
{
    extern __shared__ float sm[];
    float* As = sm;                       // [TMM][AS_LD]
    float* Ws = sm + TMM * AS_LD;         // [TNN][WS_LD]

    const int m0  = blockIdx.x * TMM;
    const int n0  = blockIdx.y * TNN;
    const int tid = threadIdx.x;
    const int warp = tid >> 5;

    wmma::fragment<wmma::accumulator, 16, 16, 8, float> cfrag[2][5];
#pragma unroll
    for (int i = 0; i < 2; i++)
#pragma unroll
        for (int j = 0; j < 5; j++)
            wmma::fill_fragment(cfrag[i][j], 0.0f);

    const int lr  = tid >> 3;            // 0..15
    const int lc4 = (tid & 7) << 2;      // 0,4,...,28

    for (int k0 = 0; k0 < K; k0 += TKK) {
        // stage A tile (rounded to tf32)
#pragma unroll
        for (int r = lr; r < TMM; r += 16) {
            int gm = m0 + r;
            float4 v = make_float4(0.f, 0.f, 0.f, 0.f);
            if (gm < M) v = *(const float4*)(A + (size_t)gm * lda + k0 + lc4);
            v.x = wmma::__float_to_tf32(v.x); v.y = wmma::__float_to_tf32(v.y);
            v.z = wmma::__float_to_tf32(v.z); v.w = wmma::__float_to_tf32(v.w);
            *(float4*)(As + r * AS_LD + lc4) = v;
        }
        // stage W tile (rounded to tf32)
#pragma unroll
        for (int r = lr; r < TNN; r += 16) {
            int gn = n0 + r;
            float4 v = make_float4(0.f, 0.f, 0.f, 0.f);
            if (gn < N) v = *(const float4*)(W + (size_t)gn * ldw + k0 + lc4);
            v.x = wmma::__float_to_tf32(v.x); v.y = wmma::__float_to_tf32(v.y);
            v.z = wmma::__float_to_tf32(v.z); v.w = wmma::__float_to_tf32(v.w);
            *(float4*)(Ws + r * WS_LD + lc4) = v;
        }
        __syncthreads();

#pragma unroll
        for (int kk = 0; kk < TKK; kk += 8) {
            wmma::fragment<wmma::matrix_a, 16, 16, 8, wmma::precision::tf32, wmma::row_major> afrag[2];
            wmma::fragment<wmma::matrix_b, 16, 16, 8, wmma::precision::tf32, wmma::col_major> bfrag[5];
#pragma unroll
            for (int i = 0; i < 2; i++)
                wmma::load_matrix_sync(afrag[i], As + (warp * 32 + i * 16) * AS_LD + kk, AS_LD);
#pragma unroll
            for (int j = 0; j < 5; j++)
                wmma::load_matrix_sync(bfrag[j], Ws + (j * 16) * WS_LD + kk, WS_LD);
#pragma unroll
            for (int i = 0; i < 2; i++)
#pragma unroll
                for (int j = 0; j < 5; j++)
                    wmma::mma_sync(cfrag[i][j], afrag[i], bfrag[j], cfrag[i][j]);
        }
        __syncthreads();
    }

    // stage C tile in smem (reuses As/Ws space), then bias-add + write
    float* Cs = sm;
#pragma unroll
    for (int i = 0; i < 2; i++)
#pragma unroll
        for (int j = 0; j < 5; j++)
            wmma::store_matrix_sync(Cs + (warp * 32 + i * 16) * CS_LD + j * 16,
                                    cfrag[i][j], CS_LD, wmma::mem_row_major);
    __syncthreads();

    int gm = m0 + tid;
    if (gm < M) {
        float* crow = C + (size_t)gm * ldc;
#pragma unroll
        for (int c = 0; c < TNN; c += 4) {
            int gn = n0 + c;
            if (gn + 3 < N) {
                float4 v = *(float4*)(Cs + tid * CS_LD + c);
                v.x += bias[gn + 0]; v.y += bias[gn + 1];
                v.z += bias[gn + 2]; v.w += bias[gn + 3];
                *(float4*)(crow + gn) = v;
            } else {
                for (int u = 0; u < 4; u++)
                    if (gn + u < N) crow[gn + u] = Cs[tid * CS_LD + c + u] + bias[gn + u];
            }
        }
    }
}

// ============ skinny fp32 GEMM for M=64 recurrent steps ============
// C[64,N] = A[64,K] @ W[N,K]^T + bias ; grid.x = N/8, block = 256
__global__ void __launch_bounds__(256)
skinny_gemm(const float* __restrict__ A, const float* __restrict__ W,
            const float* __restrict__ bias, float* __restrict__ C,
            int N, int K)
{
    int n0 = blockIdx.x * 8;
    int m  = threadIdx.x & 63;
    int g  = threadIdx.x >> 6;           // 0..3
    const float4* a  = (const float4*)(A + (size_t)m * K);
    const float4* w0 = (const float4*)(W + (size_t)(n0 + g) * K);
    const float4* w1 = (const float4*)(W + (size_t)(n0 + g + 4) * K);
    float s0 = 0.f, s1 = 0.f;
    int k4 = K >> 2;
#pragma unroll 8
    for (int i = 0; i < k4; i++) {
        float4 av = a[i], b0 = w0[i], b1 = w1[i];
        s0 += av.x * b0.x + av.y * b0.y + av.z * b0.z + av.w * b0.w;
        s1 += av.x * b1.x + av.y * b1.y + av.z * b1.z + av.w * b1.w;
    }
    C[(size_t)m * N + n0 + g]     = s0 + bias[n0 + g];
    C[(size_t)m * N + n0 + g + 4] = s1 + bias[n0 + g + 4];
}

// ---------------- generic tiled fp32 SGEMM (kept for the word loop) --------
template <int ACT>   // 0 = none, 1 = tanh
__global__ void __launch_bounds__(256)
sgemm_tn(const float* __restrict__ A, int lda,
         const float* __restrict__ W, int ldw,
         const float* __restrict__ bias,
         float* __restrict__ C, int ldc,
         int M, int N, int K)
{
    __shared__ float As[16][68];
    __shared__ float Bs[16][68];

    const int m0  = blockIdx.x * 64;
    const int n0  = blockIdx.y * 64;
    const int tid = threadIdx.x;
    const int tx  = tid & 15;
    const int ty  = tid >> 4;

    const int lrow = tid >> 2;
    const int lcol = (tid & 3) * 4;

    const bool aval = (m0 + lrow) < M;
    const bool wval = (n0 + lrow) < N;
    const float* Ap = A + (size_t)(m0 + lrow) * lda + lcol;
    const float* Wp = W + (size_t)(n0 + lrow) * ldw + lcol;

    float acc[4][4] = {};

    for (int k0 = 0; k0 < K; k0 += 16) {
        float4 av = aval ? *(const float4*)(Ap + k0) : make_float4(0.f, 0.f, 0.f, 0.f);
        float4 wv = wval ? *(const float4*)(Wp + k0) : make_float4(0.f, 0.f, 0.f, 0.f);
        As[lcol + 0][lrow] = av.x; As[lcol + 1][lrow] = av.y;
        As[lcol + 2][lrow] = av.z; As[lcol + 3][lrow] = av.w;
        Bs[lcol + 0][lrow] = wv.x; Bs[lcol + 1][lrow] = wv.y;
        Bs[lcol + 2][lrow] = wv.z; Bs[lcol + 3][lrow] = wv.w;
        __syncthreads();
#pragma unroll
        for (int kk = 0; kk < 16; kk++) {
            float4 a = *(const float4*)&As[kk][ty * 4];
            float4 b = *(const float4*)&Bs[kk][tx * 4];
            acc[0][0] += a.x * b.x; acc[0][1] += a.x * b.y; acc[0][2] += a.x * b.z; acc[0][3] += a.x * b.w;
            acc[1][0] += a.y * b.x; acc[1][1] += a.y * b.y; acc[1][2] += a.y * b.z; acc[1][3] += a.y * b.w;
            acc[2][0] += a.z * b.x; acc[2][1] += a.z * b.y; acc[2][2] += a.z * b.z; acc[2][3] += a.z * b.w;
            acc[3][0] += a.w * b.x; acc[3][1] += a.w * b.y; acc[3][2] += a.w * b.z; acc[3][3] += a.w * b.w;
        }
        __syncthreads();
    }

#pragma unroll
    for (int i = 0; i < 4; i++) {
        int m = m0 + ty * 4 + i;
        if (m >= M) continue;
#pragma unroll
        for (int j = 0; j < 4; j++) {
            int n = n0 + tx * 4 + j;
            if (n >= N) continue;
            float v = acc[i][j] + (bias ? bias[n] : 0.f);
            if (ACT == 1) v = tanhf(v);
            C[(size_t)m * ldc + n] = v;
        }
    }
}

// ---------------- small kernels ----------------
__global__ void mean_kernel(const float* __restrict__ sp)
{
    int b = blockIdx.x;
    for (int e = threadIdx.x; e < ENC; e += blockDim.x) {
        float s = 0.f;
        for (int n = 0; n < NSP; n++) s += sp[((size_t)b * NSP + n) * ENC + e];
        d_gf[b * ENC + e] = s * (1.0f / 49.0f);
    }
}

__device__ __forceinline__ float sigmf(float x) { return 1.0f / (1.0f + expf(-x)); }

__global__ void sgru_gate(int i)
{
    int b = blockIdx.x, j = threadIdx.x;
    float gr = d_gis[b * G3 + j]            + d_ghs[b * G3 + j];
    float gz = d_gis[b * G3 + DEC + j]      + d_ghs[b * G3 + DEC + j];
    float gni = d_gis[b * G3 + 2 * DEC + j];
    float gnh = d_ghs[b * G3 + 2 * DEC + j];
    float h  = d_hs[b * DEC + j];
    float r  = sigmf(gr);
    float z  = sigmf(gz);
    float n  = tanhf(gni + r * gnh);
    float hn = (1.0f - z) * n + z * h;
    d_hs[b * DEC + j] = hn;
    d_HS[(size_t)i * BB * DEC + b * DEC + j] = hn;
}

__global__ void policy_stop_kernel(const float* __restrict__ pW, const float* __restrict__ pb,
                                   const float* __restrict__ sW, const float* __restrict__ sb,
                                   float* __restrict__ out)
{
    int row = blockIdx.x;            // i*BB + b (HS row)
    int i = row >> 6, b = row & 63;
    int warp = threadIdx.x >> 5, lane = threadIdx.x & 31;
    const float* h = d_HS + (size_t)row * DEC;
    const float* w = (warp < 5) ? (pW + warp * DEC) : sW;
    float s = 0.f;
    for (int k = lane; k < DEC; k += 32) s += h[k] * w[k];
#pragma unroll
    for (int o = 16; o; o >>= 1) s += __shfl_xor_sync(0xffffffff, s, o);
    if (lane == 0) {
        if (warp < 5) out[(b * MSN + i) * 5 + warp] = s + pb[warp];
        else          out[BB * MSN * 5 + b * MSN + i] = s + sb[0];
    }
}

__global__ void gather_emb(const int* __restrict__ tw, const float* __restrict__ embW)
{
    int idx = blockIdx.x * blockDim.x + threadIdx.x;
    const int total = MWN * BW * (EMBD / 4);        // 1,310,720
    if (idx >= total) return;
    int c4 = idx & 127;
    int r  = (idx >> 7) & 511;
    int t  = idx >> 16;
    int b = r & 63, s = r >> 6;
    int w = (t == 0) ? 1 : tw[b * MSN * MWN + s * MWN + (t - 1)];
    float4 v = *(const float4*)(embW + (size_t)w * EMBD + c4 * 4);
    *(float4*)(&d_EMBT[((size_t)t * BW + r) * EMBD + c4 * 4]) = v;
}

__global__ void copyH_kernel()
{
    int i = blockIdx.x * blockDim.x + threadIdx.x;
    d_H[i] = d_HS[i];
}

// attention for one word step: e = relu(att1[b] + att2[r]) . wfull + bf ; softmax; ctx
__global__ void __launch_bounds__(256)
attn_kernel(const float* __restrict__ sp,
            const float* __restrict__ wfull, const float* __restrict__ bfull)
{
    __shared__ float a2[EMBD];
    __shared__ float e[64];
    __shared__ float alpha[64];

    int r = blockIdx.x;
    int b = r & (BB - 1);
    int tid = threadIdx.x;
    int warp = tid >> 5, lane = tid & 31;

    for (int k = tid; k < EMBD; k += 256) a2[k] = d_att2[(size_t)r * EMBD + k];
    __syncthreads();

    for (int n = warp; n < NSP; n += 8) {
        const float* a1 = d_att1 + ((size_t)(b * NSP + n)) * EMBD;
        float s = 0.f;
        for (int k = lane; k < EMBD; k += 32) {
            float v = a1[k] + a2[k];
            v = fmaxf(v, 0.f);
            s += v * wfull[k];
        }
#pragma unroll
        for (int o = 16; o; o >>= 1) s += __shfl_xor_sync(0xffffffff, s, o);
        if (lane == 0) e[n] = s + bfull[0];
    }
    __syncthreads();

    if (warp == 0) {
        float m = -1e30f;
        for (int n = lane; n < NSP; n += 32) m = fmaxf(m, e[n]);
#pragma unroll
        for (int o = 16; o; o >>= 1) m = fmaxf(m, __shfl_xor_sync(0xffffffff, m, o));
        float ssum = 0.f;
        for (int n = lane; n < NSP; n += 32) { float t = expf(e[n] - m); alpha[n] = t; ssum += t; }
#pragma unroll
        for (int o = 16; o; o >>= 1) ssum += __shfl_xor_sync(0xffffffff, ssum, o);
        float inv = 1.0f / ssum;
        for (int n = lane; n < NSP; n += 32) alpha[n] *= inv;
    }
    __syncthreads();

    for (int c = tid; c < ENC; c += 256) {
        float s = 0.f;
#pragma unroll 7
        for (int n = 0; n < NSP; n++) s += alpha[n] * sp[((size_t)(b * NSP + n)) * ENC + c];
        d_ctx[(size_t)r * ENC + c] = s;
    }
}

__global__ void wgru_gate(int t)
{
    int r = blockIdx.x, j = threadIdx.x;
    size_t eb = ((size_t)t * BW + r) * G3;
    size_t rb = (size_t)r * G3;
    float gir = d_EMBGI[eb + j]           + d_gictx[rb + j];
    float giz = d_EMBGI[eb + DEC + j]     + d_gictx[rb + DEC + j];
    float gin = d_EMBGI[eb + 2 * DEC + j] + d_gictx[rb + 2 * DEC + j];
    float ghr = d_ghw[rb + j];
    float ghz = d_ghw[rb + DEC + j];
    float ghn = d_ghw[rb + 2 * DEC + j];
    float h   = d_H[(size_t)r * DEC + j];
    float rg = sigmf(gir + ghr);
    float z  = sigmf(giz + ghz);
    float n  = tanhf(gin + rg * ghn);
    float hn = (1.0f - z) * n + z * h;
    d_H[(size_t)r * DEC + j] = hn;
    int b = r & 63, s = r >> 6;
    d_Hall[((size_t)((b * MSN + s) * MWN + t)) * DEC + j] = hn;
}

// ---------------- cached scratch addresses ----------------
static float *gf, *hs, *gis, *ghs, *att1, *embt, *embgi, *H, *Hall,
             *att2, *ctx, *gictx, *ghw;
static bool g_init = false;

static void resolve_scratch()
{
    cudaGetSymbolAddress((void**)&gf,    d_gf);
    cudaGetSymbolAddress((void**)&hs,    d_hs);
    cudaGetSymbolAddress((void**)&gis,   d_gis);
    cudaGetSymbolAddress((void**)&ghs,   d_ghs);
    cudaGetSymbolAddress((void**)&att1,  d_att1);
    cudaGetSymbolAddress((void**)&embt,  d_EMBT);
    cudaGetSymbolAddress((void**)&embgi, d_EMBGI);
    cudaGetSymbolAddress((void**)&H,     d_H);
    cudaGetSymbolAddress((void**)&Hall,  d_Hall);
    cudaGetSymbolAddress((void**)&att2,  d_att2);
    cudaGetSymbolAddress((void**)&ctx,   d_ctx);
    cudaGetSymbolAddress((void**)&gictx, d_gictx);
    cudaGetSymbolAddress((void**)&ghw,   d_ghw);
    g_init = true;
}

// ---------------- host launcher ----------------
extern "C" void kernel_launch(void* const* d_in, const int* in_sizes, int n_in,
                              void* d_out, int out_size)
{
    if (!g_init) resolve_scratch();

    const float* spatial    = (const float*)d_in[0];
    const int*   tw         = (const int*)  d_in[1];
    const float* emb_W      = (const float*)d_in[2];
    const float* s_W_ih     = (const float*)d_in[3];
    const float* s_W_hh     = (const float*)d_in[4];
    const float* s_b_ih     = (const float*)d_in[5];
    const float* s_b_hh     = (const float*)d_in[6];
    const float* policy_W   = (const float*)d_in[7];
    const float* policy_b   = (const float*)d_in[8];
    const float* stop_W     = (const float*)d_in[9];
    const float* stop_b     = (const float*)d_in[10];
    const float* att_enc_W  = (const float*)d_in[11];
    const float* att_enc_b  = (const float*)d_in[12];
    const float* att_dec_W  = (const float*)d_in[13];
    const float* att_dec_b  = (const float*)d_in[14];
    const float* att_full_W = (const float*)d_in[15];
    const float* att_full_b = (const float*)d_in[16];
    const float* w_W_ih     = (const float*)d_in[17];
    const float* w_W_hh     = (const float*)d_in[18];
    const float* w_b_ih     = (const float*)d_in[19];
    const float* w_b_hh     = (const float*)d_in[20];
    const float* fc_W       = (const float*)d_in[21];
    const float* fc_b       = (const float*)d_in[22];
    const float* init_W     = (const float*)d_in[23];
    const float* init_b     = (const float*)d_in[24];
    float* out = (float*)d_out;

    // ---- setup ----
    mean_kernel<<<BB, 256>>>(spatial);
    sgemm_tn<1><<<dim3(1, 8), 256>>>(gf, ENC, init_W, ENC, init_b, hs, DEC, BB, DEC, ENC);
    sgemm_tn<0><<<dim3(49, 8), 256>>>(spatial, ENC, att_enc_W, ENC, att_enc_b,
                                      att1, EMBD, BB * NSP, EMBD, ENC);
    sgemm_tn<0><<<dim3(1, 24), 256>>>(gf, ENC, s_W_ih, ENC, s_b_ih, gis, G3, BB, G3, ENC);

    // ---- sentence GRU: 8 tiny sequential steps (skinny latency-tuned GEMM) ----
    for (int i = 0; i < MSN; i++) {
        skinny_gemm<<<G3 / 8, 256>>>(hs, s_W_hh, s_b_hh, ghs, G3, DEC);
        sgru_gate<<<BB, DEC>>>(i);
    }
    policy_stop_kernel<<<MSN * BB, 192>>>(policy_W, policy_b, stop_W, stop_b, out);

    // ---- batched precomputes for word RNN ----
    gather_emb<<<(MWN * BW * (EMBD / 4) + 255) / 256, 256>>>(tw, emb_W);
    // EMBGI[t] = emb_t @ W_ih[:, :EMB].T + b_ih  — tf32 tensor cores
    mma_gemm<<<dim3(MWN * BW / TMM, (G3 + TNN - 1) / TNN), 128, MMA_SMEM_BYTES>>>(
        embt, EMBD, w_W_ih, EMBD + ENC, w_b_ih, embgi, G3, MWN * BW, G3, EMBD);
    copyH_kernel<<<512, 512>>>();   // H init = HS (identical layout)

    // ---- word RNN: 20 sequential steps over 512 batched rows (fp32) ----
    for (int t = 0; t < MWN; t++) {
        sgemm_tn<0><<<dim3(8, 8), 256>>>(H, DEC, att_dec_W, DEC, att_dec_b,
                                         att2, EMBD, BW, EMBD, DEC);
        attn_kernel<<<BW, 256>>>(spatial, att_full_W, att_full_b);
        sgemm_tn<0><<<dim3(8, 24), 256>>>(ctx, ENC, w_W_ih + EMBD, G3, (const float*)nullptr,
                                          gictx, G3, BW, G3, ENC);
        sgemm_tn<0><<<dim3(8, 24), 256>>>(H, DEC, w_W_hh, DEC, w_b_hh,
                                          ghw, G3, BW, G3, DEC);
        wgru_gate<<<BW, DEC>>>(t);
    }

    // ---- final vocab projection: tf32 tensor cores straight into the output ----
    // 10240 = 80*128 tiles in M, 10000 = 125*80 tiles in N: exact tiling
    mma_gemm<<<dim3(MWN * BW / TMM, VOC / TNN), 128, MMA_SMEM_BYTES>>>(
        Hall, DEC, fc_W, DEC, fc_b, out + 3072, VOC, MWN * BW, VOC, DEC);
}

// round 4
// speedup vs baseline: 1.3178x; 1.0257x over previous
#include <cuda_runtime.h>
#include <mma.h>
using namespace nvcuda;

// ---------------- problem constants ----------------
#define BB    64      // batch
#define NSP   49      // spatial positions
#define ENC   1024
#define DEC   512
#define EMBD  512
#define VOC   10000
#define MSN   8       // max sentences
#define MWN   20      // max words
#define BW    512     // MSN*BB : batched word-RNN rows
#define G3    1536    // 3*DEC

// ---------------- device scratch (static, no allocation) ----------------
__device__ float d_gf   [BB * ENC];
__device__ float d_hs   [BB * DEC];
__device__ float d_gis  [BB * G3];
__device__ float d_ghs  [BB * G3];
__device__ float d_HS   [MSN * BB * DEC];
__device__ float d_att1 [BB * NSP * EMBD];
__device__ float d_EMBT [MWN * BW * EMBD];
__device__ float d_EMBGI[MWN * BW * G3];
__device__ float d_H    [BW * DEC];
__device__ float d_Hall [MWN * BW * DEC];
__device__ float d_att2 [BW * EMBD];
__device__ float d_ctx  [BW * ENC];
__device__ float d_gictx[BW * G3];
__device__ float d_ghw  [BW * G3];

// ================= tf32 tensor-core GEMM: C = A @ W^T + bias =================
// A: [M,K] row-major (lda), W: [N,K] row-major (ldw), C: [M,N] (ldc).
// Block tile 128x80, 4 warps, warp tile 32x80 (2x5 wmma 16x16k8 frags).
// K must be a multiple of 32. Values pre-rounded to tf32 (RNA) in smem.
#define TMM 128
#define TNN 80
#define TKK 32
#define AS_LD 36
#define WS_LD 36
#define CS_LD 84
#define MMA_SMEM_BYTES (TMM * CS_LD * 4)   // 43008 B  (>= (TMM+TNN)*36*4)

__global__ void __launch_bounds__(128)
mma_gemm(const float* __restrict__ A, int lda,
         const float* __restrict__ W, int ldw,
         const float* __restrict__ bias,
         float* __restrict__ C, int ldc,
         int M, int N, int K)
{
    extern __shared__ float sm[];
    float* As = sm;                       // [TMM][AS_LD]
    float* Ws = sm + TMM * AS_LD;         // [TNN][WS_LD]

    const int m0  = blockIdx.x * TMM;
    const int n0  = blockIdx.y * TNN;
    const int tid = threadIdx.x;
    const int warp = tid >> 5;

    wmma::fragment<wmma::accumulator, 16, 16, 8, float> cfrag[2][5];
#pragma unroll
    for (int i = 0; i < 2; i++)
#pragma unroll
        for (int j = 0; j < 5; j++)
            wmma::fill_fragment(cfrag[i][j], 0.0f);

    const int lr  = tid >> 3;            // 0..15
    const int lc4 = (tid & 7) << 2;      // 0,4,...,28

    for (int k0 = 0; k0 < K; k0 += TKK) {
        // stage A tile (rounded to tf32)
#pragma unroll
        for (int r = lr; r < TMM; r += 16) {
            int gm = m0 + r;
            float4 v = make_float4(0.f, 0.f, 0.f, 0.f);
            if (gm < M) v = *(const float4*)(A + (size_t)gm * lda + k0 + lc4);
            v.x = wmma::__float_to_tf32(v.x); v.y = wmma::__float_to_tf32(v.y);
            v.z = wmma::__float_to_tf32(v.z); v.w = wmma::__float_to_tf32(v.w);
            *(float4*)(As + r * AS_LD + lc4) = v;
        }
        // stage W tile (rounded to tf32)
#pragma unroll
        for (int r = lr; r < TNN; r += 16) {
            int gn = n0 + r;
            float4 v = make_float4(0.f, 0.f, 0.f, 0.f);
            if (gn < N) v = *(const float4*)(W + (size_t)gn * ldw + k0 + lc4);
            v.x = wmma::__float_to_tf32(v.x); v.y = wmma::__float_to_tf32(v.y);
            v.z = wmma::__float_to_tf32(v.z); v.w = wmma::__float_to_tf32(v.w);
            *(float4*)(Ws + r * WS_LD + lc4) = v;
        }
        __syncthreads();

#pragma unroll
        for (int kk = 0; kk < TKK; kk += 8) {
            wmma::fragment<wmma::matrix_a, 16, 16, 8, wmma::precision::tf32, wmma::row_major> afrag[2];
            wmma::fragment<wmma::matrix_b, 16, 16, 8, wmma::precision::tf32, wmma::col_major> bfrag[5];
#pragma unroll
            for (int i = 0; i < 2; i++)
                wmma::load_matrix_sync(afrag[i], As + (warp * 32 + i * 16) * AS_LD + kk, AS_LD);
#pragma unroll
            for (int j = 0; j < 5; j++)
                wmma::load_matrix_sync(bfrag[j], Ws + (j * 16) * WS_LD + kk, WS_LD);
#pragma unroll
            for (int i = 0; i < 2; i++)
#pragma unroll
                for (int j = 0; j < 5; j++)
                    wmma::mma_sync(cfrag[i][j], afrag[i], bfrag[j], cfrag[i][j]);
        }
        __syncthreads();
    }

    // stage C tile in smem (reuses As/Ws space), then bias-add + write
    float* Cs = sm;
#pragma unroll
    for (int i = 0; i < 2; i++)
#pragma unroll
        for (int j = 0; j < 5; j++)
            wmma::store_matrix_sync(Cs + (warp * 32 + i * 16) * CS_LD + j * 16,
                                    cfrag[i][j], CS_LD, wmma::mem_row_major);
    __syncthreads();

    int gm = m0 + tid;
    if (gm < M) {
        float* crow = C + (size_t)gm * ldc;
#pragma unroll
        for (int c = 0; c < TNN; c += 4) {
            int gn = n0 + c;
            if (gn + 3 < N) {
                float4 v = *(float4*)(Cs + tid * CS_LD + c);
                if (bias) {
                    v.x += bias[gn + 0]; v.y += bias[gn + 1];
                    v.z += bias[gn + 2]; v.w += bias[gn + 3];
                }
                *(float4*)(crow + gn) = v;
            } else {
                for (int u = 0; u < 4; u++)
                    if (gn + u < N)
                        crow[gn + u] = Cs[tid * CS_LD + c + u] + (bias ? bias[gn + u] : 0.f);
            }
        }
    }
}

// ============ skinny fp32 GEMM for M=64 latency-critical steps ============
// C[64,N] = act(A[64,K] @ W[N,K]^T + bias) ; grid.x = N/8, block = 256
template <int ACT>   // 0 = none, 1 = tanh
__global__ void __launch_bounds__(256)
skinny_gemm(const float* __restrict__ A, const float* __restrict__ W,
            const float* __restrict__ bias, float* __restrict__ C,
            int N, int K)
{
    int n0 = blockIdx.x * 8;
    int m  = threadIdx.x & 63;
    int g  = threadIdx.x >> 6;           // 0..3
    const float4* a  = (const float4*)(A + (size_t)m * K);
    const float4* w0 = (const float4*)(W + (size_t)(n0 + g) * K);
    const float4* w1 = (const float4*)(W + (size_t)(n0 + g + 4) * K);
    float s0 = 0.f, s1 = 0.f;
    int k4 = K >> 2;
#pragma unroll 8
    for (int i = 0; i < k4; i++) {
        float4 av = a[i], b0 = w0[i], b1 = w1[i];
        s0 += av.x * b0.x + av.y * b0.y + av.z * b0.z + av.w * b0.w;
        s1 += av.x * b1.x + av.y * b1.y + av.z * b1.z + av.w * b1.w;
    }
    s0 += bias[n0 + g];
    s1 += bias[n0 + g + 4];
    if (ACT == 1) { s0 = tanhf(s0); s1 = tanhf(s1); }
    C[(size_t)m * N + n0 + g]     = s0;
    C[(size_t)m * N + n0 + g + 4] = s1;
}

// ---------------- small kernels ----------------
__global__ void mean_kernel(const float* __restrict__ sp)
{
    int b = blockIdx.x;
    for (int e = threadIdx.x; e < ENC; e += blockDim.x) {
        float s = 0.f;
        for (int n = 0; n < NSP; n++) s += sp[((size_t)b * NSP + n) * ENC + e];
        d_gf[b * ENC + e] = s * (1.0f / 49.0f);
    }
}

__device__ __forceinline__ float sigmf(float x) { return 1.0f / (1.0f + expf(-x)); }

__global__ void sgru_gate(int i)
{
    int b = blockIdx.x, j = threadIdx.x;
    float gr = d_gis[b * G3 + j]            + d_ghs[b * G3 + j];
    float gz = d_gis[b * G3 + DEC + j]      + d_ghs[b * G3 + DEC + j];
    float gni = d_gis[b * G3 + 2 * DEC + j];
    float gnh = d_ghs[b * G3 + 2 * DEC + j];
    float h  = d_hs[b * DEC + j];
    float r  = sigmf(gr);
    float z  = sigmf(gz);
    float n  = tanhf(gni + r * gnh);
    float hn = (1.0f - z) * n + z * h;
    d_hs[b * DEC + j] = hn;
    d_HS[(size_t)i * BB * DEC + b * DEC + j] = hn;
}

__global__ void policy_stop_kernel(const float* __restrict__ pW, const float* __restrict__ pb,
                                   const float* __restrict__ sW, const float* __restrict__ sb,
                                   float* __restrict__ out)
{
    int row = blockIdx.x;            // i*BB + b (HS row)
    int i = row >> 6, b = row & 63;
    int warp = threadIdx.x >> 5, lane = threadIdx.x & 31;
    const float* h = d_HS + (size_t)row * DEC;
    const float* w = (warp < 5) ? (pW + warp * DEC) : sW;
    float s = 0.f;
    for (int k = lane; k < DEC; k += 32) s += h[k] * w[k];
#pragma unroll
    for (int o = 16; o; o >>= 1) s += __shfl_xor_sync(0xffffffff, s, o);
    if (lane == 0) {
        if (warp < 5) out[(b * MSN + i) * 5 + warp] = s + pb[warp];
        else          out[BB * MSN * 5 + b * MSN + i] = s + sb[0];
    }
}

__global__ void gather_emb(const int* __restrict__ tw, const float* __restrict__ embW)
{
    int idx = blockIdx.x * blockDim.x + threadIdx.x;
    const int total = MWN * BW * (EMBD / 4);        // 1,310,720
    if (idx >= total) return;
    int c4 = idx & 127;
    int r  = (idx >> 7) & 511;
    int t  = idx >> 16;
    int b = r & 63, s = r >> 6;
    int w = (t == 0) ? 1 : tw[b * MSN * MWN + s * MWN + (t - 1)];
    float4 v = *(const float4*)(embW + (size_t)w * EMBD + c4 * 4);
    *(float4*)(&d_EMBT[((size_t)t * BW + r) * EMBD + c4 * 4]) = v;
}

__global__ void copyH_kernel()
{
    int i = blockIdx.x * blockDim.x + threadIdx.x;
    d_H[i] = d_HS[i];
}

// attention for one word step: e = relu(att1[b] + att2[r]) . wfull + bf ; softmax; ctx
__global__ void __launch_bounds__(256)
attn_kernel(const float* __restrict__ sp,
            const float* __restrict__ wfull, const float* __restrict__ bfull)
{
    __shared__ float a2[EMBD];
    __shared__ float e[64];
    __shared__ float alpha[64];

    int r = blockIdx.x;
    int b = r & (BB - 1);
    int tid = threadIdx.x;
    int warp = tid >> 5, lane = tid & 31;

    for (int k = tid; k < EMBD; k += 256) a2[k] = d_att2[(size_t)r * EMBD + k];
    __syncthreads();

    for (int n = warp; n < NSP; n += 8) {
        const float* a1 = d_att1 + ((size_t)(b * NSP + n)) * EMBD;
        float s = 0.f;
        for (int k = lane; k < EMBD; k += 32) {
            float v = a1[k] + a2[k];
            v = fmaxf(v, 0.f);
            s += v * wfull[k];
        }
#pragma unroll
        for (int o = 16; o; o >>= 1) s += __shfl_xor_sync(0xffffffff, s, o);
        if (lane == 0) e[n] = s + bfull[0];
    }
    __syncthreads();

    if (warp == 0) {
        float m = -1e30f;
        for (int n = lane; n < NSP; n += 32) m = fmaxf(m, e[n]);
#pragma unroll
        for (int o = 16; o; o >>= 1) m = fmaxf(m, __shfl_xor_sync(0xffffffff, m, o));
        float ssum = 0.f;
        for (int n = lane; n < NSP; n += 32) { float t = expf(e[n] - m); alpha[n] = t; ssum += t; }
#pragma unroll
        for (int o = 16; o; o >>= 1) ssum += __shfl_xor_sync(0xffffffff, ssum, o);
        float inv = 1.0f / ssum;
        for (int n = lane; n < NSP; n += 32) alpha[n] *= inv;
    }
    __syncthreads();

    for (int c = tid; c < ENC; c += 256) {
        float s = 0.f;
#pragma unroll 7
        for (int n = 0; n < NSP; n++) s += alpha[n] * sp[((size_t)(b * NSP + n)) * ENC + c];
        d_ctx[(size_t)r * ENC + c] = s;
    }
}

__global__ void wgru_gate(int t)
{
    int r = blockIdx.x, j = threadIdx.x;
    size_t eb = ((size_t)t * BW + r) * G3;
    size_t rb = (size_t)r * G3;
    float gir = d_EMBGI[eb + j]           + d_gictx[rb + j];
    float giz = d_EMBGI[eb + DEC + j]     + d_gictx[rb + DEC + j];
    float gin = d_EMBGI[eb + 2 * DEC + j] + d_gictx[rb + 2 * DEC + j];
    float ghr = d_ghw[rb + j];
    float ghz = d_ghw[rb + DEC + j];
    float ghn = d_ghw[rb + 2 * DEC + j];
    float h   = d_H[(size_t)r * DEC + j];
    float rg = sigmf(gir + ghr);
    float z  = sigmf(giz + ghz);
    float n  = tanhf(gin + rg * ghn);
    float hn = (1.0f - z) * n + z * h;
    d_H[(size_t)r * DEC + j] = hn;
    int b = r & 63, s = r >> 6;
    d_Hall[((size_t)((b * MSN + s) * MWN + t)) * DEC + j] = hn;
}

// ---------------- cached scratch addresses ----------------
static float *gf, *hs, *gis, *ghs, *att1, *embt, *embgi, *H, *Hall,
             *att2, *ctx, *gictx, *ghw;
static bool g_init = false;

static void resolve_scratch()
{
    cudaGetSymbolAddress((void**)&gf,    d_gf);
    cudaGetSymbolAddress((void**)&hs,    d_hs);
    cudaGetSymbolAddress((void**)&gis,   d_gis);
    cudaGetSymbolAddress((void**)&ghs,   d_ghs);
    cudaGetSymbolAddress((void**)&att1,  d_att1);
    cudaGetSymbolAddress((void**)&embt,  d_EMBT);
    cudaGetSymbolAddress((void**)&embgi, d_EMBGI);
    cudaGetSymbolAddress((void**)&H,     d_H);
    cudaGetSymbolAddress((void**)&Hall,  d_Hall);
    cudaGetSymbolAddress((void**)&att2,  d_att2);
    cudaGetSymbolAddress((void**)&ctx,   d_ctx);
    cudaGetSymbolAddress((void**)&gictx, d_gictx);
    cudaGetSymbolAddress((void**)&ghw,   d_ghw);
    g_init = true;
}

// ---------------- host launcher ----------------
extern "C" void kernel_launch(void* const* d_in, const int* in_sizes, int n_in,
                              void* d_out, int out_size)
{
    if (!g_init) resolve_scratch();

    const float* spatial    = (const float*)d_in[0];
    const int*   tw         = (const int*)  d_in[1];
    const float* emb_W      = (const float*)d_in[2];
    const float* s_W_ih     = (const float*)d_in[3];
    const float* s_W_hh     = (const float*)d_in[4];
    const float* s_b_ih     = (const float*)d_in[5];
    const float* s_b_hh     = (const float*)d_in[6];
    const float* policy_W   = (const float*)d_in[7];
    const float* policy_b   = (const float*)d_in[8];
    const float* stop_W     = (const float*)d_in[9];
    const float* stop_b     = (const float*)d_in[10];
    const float* att_enc_W  = (const float*)d_in[11];
    const float* att_enc_b  = (const float*)d_in[12];
    const float* att_dec_W  = (const float*)d_in[13];
    const float* att_dec_b  = (const float*)d_in[14];
    const float* att_full_W = (const float*)d_in[15];
    const float* att_full_b = (const float*)d_in[16];
    const float* w_W_ih     = (const float*)d_in[17];
    const float* w_W_hh     = (const float*)d_in[18];
    const float* w_b_ih     = (const float*)d_in[19];
    const float* w_b_hh     = (const float*)d_in[20];
    const float* fc_W       = (const float*)d_in[21];
    const float* fc_b       = (const float*)d_in[22];
    const float* init_W     = (const float*)d_in[23];
    const float* init_b     = (const float*)d_in[24];
    float* out = (float*)d_out;

    // ---- setup ----
    mean_kernel<<<BB, 256>>>(spatial);
    // h0 = tanh(gf @ init_W.T + init_b)   (skinny, latency-tuned)
    skinny_gemm<1><<<DEC / 8, 256>>>(gf, init_W, init_b, hs, DEC, ENC);
    // att1 = spatial @ att_enc_W.T + att_enc_b   (tf32 tensor cores)
    mma_gemm<<<dim3((BB * NSP + TMM - 1) / TMM, (EMBD + TNN - 1) / TNN), 128, MMA_SMEM_BYTES>>>(
        spatial, ENC, att_enc_W, ENC, att_enc_b, att1, EMBD, BB * NSP, EMBD, ENC);
    // gi_s constant across sentence steps (skinny)
    skinny_gemm<0><<<G3 / 8, 256>>>(gf, s_W_ih, s_b_ih, gis, G3, ENC);

    // ---- sentence GRU: 8 tiny sequential steps ----
    for (int i = 0; i < MSN; i++) {
        skinny_gemm<0><<<G3 / 8, 256>>>(hs, s_W_hh, s_b_hh, ghs, G3, DEC);
        sgru_gate<<<BB, DEC>>>(i);
    }
    policy_stop_kernel<<<MSN * BB, 192>>>(policy_W, policy_b, stop_W, stop_b, out);

    // ---- batched precomputes for word RNN ----
    gather_emb<<<(MWN * BW * (EMBD / 4) + 255) / 256, 256>>>(tw, emb_W);
    // EMBGI[t] = emb_t @ W_ih[:, :EMB].T + b_ih  (all 20 steps, tf32)
    mma_gemm<<<dim3(MWN * BW / TMM, (G3 + TNN - 1) / TNN), 128, MMA_SMEM_BYTES>>>(
        embt, EMBD, w_W_ih, EMBD + ENC, w_b_ih, embgi, G3, MWN * BW, G3, EMBD);
    copyH_kernel<<<512, 512>>>();   // H init = HS (identical layout)

    // ---- word RNN: 20 sequential steps over 512 batched rows (all tf32 mma) ----
    const dim3 gG3(BW / TMM, (G3 + TNN - 1) / TNN);      // (4, 20)
    const dim3 gEM(BW / TMM, (EMBD + TNN - 1) / TNN);    // (4, 7)
    for (int t = 0; t < MWN; t++) {
        mma_gemm<<<gEM, 128, MMA_SMEM_BYTES>>>(H, DEC, att_dec_W, DEC, att_dec_b,
                                               att2, EMBD, BW, EMBD, DEC);
        attn_kernel<<<BW, 256>>>(spatial, att_full_W, att_full_b);
        mma_gemm<<<gG3, 128, MMA_SMEM_BYTES>>>(ctx, ENC, w_W_ih + EMBD, EMBD + ENC,
                                               (const float*)nullptr, gictx, G3, BW, G3, ENC);
        mma_gemm<<<gG3, 128, MMA_SMEM_BYTES>>>(H, DEC, w_W_hh, DEC, w_b_hh,
                                               ghw, G3, BW, G3, DEC);
        wgru_gate<<<BW, DEC>>>(t);
    }

    // ---- final vocab projection: tf32 tensor cores straight into the output ----
    mma_gemm<<<dim3(MWN * BW / TMM, VOC / TNN), 128, MMA_SMEM_BYTES>>>(
        Hall, DEC, fc_W, DEC, fc_b, out + 3072, VOC, MWN * BW, VOC, DEC);
}